// round 7
// baseline (speedup 1.0000x reference)
#include <cuda_runtime.h>
#include <cstdint>

// ---------------------------------------------------------------------------
// QuadTreeDecoder round 7
//  - packed f32x2 FMA (Blackwell FFMA2) in every hot loop: half the FMA instrs
//  - level 4 fused into l5+head (qt_l45_head): x5 never touches DRAM
//  - kernels: qt_wf, qt_l01, qt_l23, qt_l45_head
//  Activations node-major float4-interleaved: act[node][i4][b].
// ---------------------------------------------------------------------------

typedef unsigned long long u64;

__device__ float4 g_x2[(size_t)16  * 16 * 128];   // level-1 out (16 nodes)
__device__ float4 g_x4[(size_t)256 * 16 * 128];   // level-3 out (256 nodes)
__device__ float  g_wf[(size_t)1024 * 4 * 48 * 16];

// ---------------------------------------------------------------------------
// packed-f32x2 helpers
// ---------------------------------------------------------------------------
__device__ __forceinline__ void fma2(u64& d, u64 a, u64 b) {
    asm("fma.rn.f32x2 %0, %1, %2, %3;" : "=l"(d) : "l"(a), "l"(b), "l"(d));
}
__device__ __forceinline__ u64 pack2(float lo, float hi) {
    u64 r; asm("mov.b64 %0, {%1, %2};" : "=l"(r) : "f"(lo), "f"(hi)); return r;
}
__device__ __forceinline__ float fold2(u64 v) {
    float lo, hi; asm("mov.b64 {%0, %1}, %2;" : "=f"(lo), "=f"(hi) : "l"(v));
    return lo + hi;
}

// ---------------------------------------------------------------------------
__device__ __forceinline__ void stage_factor(float dst[16][64], const float* __restrict__ src,
                                             const float* __restrict__ sc, int tid)
{
    const float4* s4 = (const float4*)src;
    float4* d4 = (float4*)dst;
    if (sc) {
        for (int idx = tid; idx < 256; idx += 64) {
            float4 v = s4[idx];
            float s = __ldg(&sc[idx >> 4]);
            v.x *= s; v.y *= s; v.z *= s; v.w *= s;
            d4[idx] = v;
        }
    } else {
        for (int idx = tid; idx < 256; idx += 64)
            d4[idx] = s4[idx];
    }
}

// lat[r] = dot(x_col, fi[r])
__device__ __forceinline__ void lat_from_smem(float lat[16],
        const float (*__restrict__ fi)[64], const float4 (*__restrict__ x_s)[64], int tid)
{
    u64 acc[16];
#pragma unroll
    for (int r = 0; r < 16; r++) acc[r] = 0ull;
#pragma unroll 4
    for (int i4 = 0; i4 < 16; i4++) {
        ulonglong2 xv = *(const ulonglong2*)&x_s[i4][tid];
#pragma unroll
        for (int r = 0; r < 16; r++) {
            ulonglong2 f = *(const ulonglong2*)&fi[r][i4 * 4];
            fma2(acc[r], xv.x, f.x);
            fma2(acc[r], xv.y, f.y);
        }
    }
#pragma unroll
    for (int r = 0; r < 16; r++) lat[r] = fold2(acc[r]);
}

__device__ __forceinline__ void duppack16(u64 lp[16], const float lat[16]) {
#pragma unroll
    for (int r = 0; r < 16; r++) lp[r] = pack2(lat[r], lat[r]);
}

// x_col += F^T lat (in place, own column)
__device__ __forceinline__ void update_smem(float4 (*x_s)[64],
        const float (*__restrict__ F)[64], const u64 lp[16], int tid)
{
#pragma unroll 4
    for (int o4 = 0; o4 < 16; o4++) {
        ulonglong2 a = *(const ulonglong2*)&x_s[o4][tid];
#pragma unroll
        for (int r = 0; r < 16; r++) {
            ulonglong2 f = *(const ulonglong2*)&F[r][o4 * 4];
            fma2(a.x, lp[r], f.x);
            fma2(a.y, lp[r], f.y);
        }
        *(ulonglong2*)&x_s[o4][tid] = a;
    }
}

// out = x_col + F^T lat  ->  global interleaved
__device__ __forceinline__ void emit_global(float4* __restrict__ op,
        const float4 (*__restrict__ x_s)[64],
        const float (*__restrict__ F)[64], const u64 lp[16], int tid)
{
#pragma unroll 4
    for (int o4 = 0; o4 < 16; o4++) {
        ulonglong2 a = *(const ulonglong2*)&x_s[o4][tid];
#pragma unroll
        for (int r = 0; r < 16; r++) {
            ulonglong2 f = *(const ulonglong2*)&F[r][o4 * 4];
            fma2(a.x, lp[r], f.x);
            fma2(a.y, lp[r], f.y);
        }
        *(ulonglong2*)&op[o4 * 128] = a;
    }
}

// ---------------------------------------------------------------------------
// WF[p][c][k][r] = sum_o head_w[k][o] * F_c[341+p][r][o].  4096 blocks x 64.
// ---------------------------------------------------------------------------
__global__ __launch_bounds__(64)
void qt_wf_kernel(const float* __restrict__ ftl, const float* __restrict__ ftr,
                  const float* __restrict__ fbl, const float* __restrict__ fbr,
                  const float* __restrict__ head_w, float* __restrict__ wf)
{
    __shared__ __align__(16) float F_s[16][64];

    const int bid = blockIdx.x;
    const int p   = bid >> 2;
    const int c   = bid & 3;
    const int tid = threadIdx.x;
    const int node = 341 + p;

    const float* Fc = (c == 0 ? ftl : c == 1 ? ftr : c == 2 ? fbl : fbr)
                      + (size_t)node * 1024;
    stage_factor(F_s, Fc, nullptr, tid);
    __syncthreads();

    if (tid < 48) {
        const int k = tid;
        const ulonglong2* wrow = (const ulonglong2*)(head_w + (size_t)k * 64);
        u64 acc[16];
#pragma unroll
        for (int r = 0; r < 16; r++) acc[r] = 0ull;
#pragma unroll 4
        for (int i4 = 0; i4 < 16; i4++) {
            ulonglong2 wv = wrow[i4];
#pragma unroll
            for (int r = 0; r < 16; r++) {
                ulonglong2 f = *(const ulonglong2*)&F_s[r][i4 * 4];
                fma2(acc[r], wv.x, f.x);
                fma2(acc[r], wv.y, f.y);
            }
        }
        float* dst = wf + ((size_t)p * 4 + c) * (48 * 16) + (size_t)k * 16;
#pragma unroll
        for (int r = 0; r < 16; r += 4)
            *(float4*)(dst + r) = make_float4(fold2(acc[r]), fold2(acc[r+1]),
                                              fold2(acc[r+2]), fold2(acc[r+3]));
    }
}

// ---------------------------------------------------------------------------
// Levels 0+1 fused. bid = (p1*4 + c1)*2 + qh. 32 blocks x 64.
// ---------------------------------------------------------------------------
__global__ __launch_bounds__(64)
void qt_l01(const float* __restrict__ x0, float4* __restrict__ xout,
            const float* __restrict__ fin,
            const float* __restrict__ ftl, const float* __restrict__ ftr,
            const float* __restrict__ fbl, const float* __restrict__ fbr,
            const float* __restrict__ scale)
{
    __shared__ __align__(16) float fiA[16][64], FA[16][64], fiB[16][64], FB[16][64];
    __shared__ float4 x_s[16][64];

    const int bid = blockIdx.x;
    const int p1  = bid >> 3;
    const int c1  = (bid >> 1) & 3;
    const int qh  = bid & 1;
    const int tid = threadIdx.x;

    const float* FcA = (p1 == 0 ? ftl : p1 == 1 ? ftr : p1 == 2 ? fbl : fbr);
    const int nodeB = 1 + p1;
    const float* FcB = (c1 == 0 ? ftl : c1 == 1 ? ftr : c1 == 2 ? fbl : fbr)
                       + (size_t)nodeB * 1024;

    stage_factor(fiA, fin, scale, tid);
    stage_factor(FA,  FcA, nullptr, tid);
    stage_factor(fiB, fin + (size_t)nodeB * 1024, scale + (size_t)nodeB * 16, tid);
    stage_factor(FB,  FcB, nullptr, tid);
    {
        const int b = qh * 64 + tid;
        const float4* xp = (const float4*)(x0 + (size_t)b * 64);
#pragma unroll
        for (int i4 = 0; i4 < 16; i4++)
            x_s[i4][tid] = xp[i4];
    }
    __syncthreads();

    float lat[16]; u64 lp[16];
    lat_from_smem(lat, fiA, x_s, tid);
    duppack16(lp, lat);
    update_smem(x_s, FA, lp, tid);
    lat_from_smem(lat, fiB, x_s, tid);
    duppack16(lp, lat);

    const int gr = p1 >> 1, gc = p1 & 1;
    const int cn = (2 * gr + (c1 >> 1)) * 4 + 2 * gc + (c1 & 1);
    float4* op = xout + ((size_t)cn * 16) * 128 + qh * 64 + tid;
    emit_global(op, x_s, FB, lp, tid);
}

// ---------------------------------------------------------------------------
// Levels 2+3 fused. bid = (p3*4 + c3)*2 + qh. 512 blocks x 64.
// ---------------------------------------------------------------------------
__global__ __launch_bounds__(64)
void qt_l23(const float4* __restrict__ xin, float4* __restrict__ xout,
            const float* __restrict__ fin,
            const float* __restrict__ ftl, const float* __restrict__ ftr,
            const float* __restrict__ fbl, const float* __restrict__ fbr,
            const float* __restrict__ scale)
{
    __shared__ __align__(16) float fiA[16][64], FA[16][64], fiB[16][64], FB[16][64];
    __shared__ float4 x_s[16][64];

    const int bid = blockIdx.x;
    const int p3  = bid >> 3;
    const int c3  = (bid >> 1) & 3;
    const int qh  = bid & 1;
    const int tid = threadIdx.x;

    const int r3 = p3 >> 3, k3 = p3 & 7;
    const int p2 = (r3 >> 1) * 4 + (k3 >> 1);
    const int c2 = ((r3 & 1) << 1) | (k3 & 1);

    const int nodeA = 5 + p2;
    const int nodeB = 21 + p3;
    const float* FcA = (c2 == 0 ? ftl : c2 == 1 ? ftr : c2 == 2 ? fbl : fbr)
                       + (size_t)nodeA * 1024;
    const float* FcB = (c3 == 0 ? ftl : c3 == 1 ? ftr : c3 == 2 ? fbl : fbr)
                       + (size_t)nodeB * 1024;

    stage_factor(fiA, fin + (size_t)nodeA * 1024, scale + (size_t)nodeA * 16, tid);
    stage_factor(FA,  FcA, nullptr, tid);
    stage_factor(fiB, fin + (size_t)nodeB * 1024, scale + (size_t)nodeB * 16, tid);
    stage_factor(FB,  FcB, nullptr, tid);
    {
        const float4* xp = xin + ((size_t)p2 * 16) * 128 + qh * 64 + tid;
#pragma unroll
        for (int i4 = 0; i4 < 16; i4++)
            x_s[i4][tid] = xp[i4 * 128];
    }
    __syncthreads();

    float lat[16]; u64 lp[16];
    lat_from_smem(lat, fiA, x_s, tid);
    duppack16(lp, lat);
    update_smem(x_s, FA, lp, tid);
    lat_from_smem(lat, fiB, x_s, tid);
    duppack16(lp, lat);

    const int gr = p3 >> 3, gc = p3 & 7;
    const int cn = (2 * gr + (c3 >> 1)) * 16 + 2 * gc + (c3 & 1);
    float4* op = xout + ((size_t)cn * 16) * 128 + qh * 64 + tid;
    emit_global(op, x_s, FB, lp, tid);
}

// ---------------------------------------------------------------------------
// Levels 4+5 + head fused. bid = p*2 + qh (2048 blocks x 64), p = level-5 node
// (grid-32 order). Derives level-4 parent, applies level-4 transform in smem,
// then lat5 / wx / 4 children -> pixels.
// ---------------------------------------------------------------------------
__global__ __launch_bounds__(64)
void qt_l45_head(const float4* __restrict__ xin,
                 const float* __restrict__ fin,
                 const float* __restrict__ ftl, const float* __restrict__ ftr,
                 const float* __restrict__ fbl, const float* __restrict__ fbr,
                 const float* __restrict__ scale,
                 const float* __restrict__ wf,
                 const float* __restrict__ head_w, const float* __restrict__ head_b,
                 float* __restrict__ out)
{
    __shared__ __align__(16) float fiA[16][64], FA[16][64], fiB[16][64];
    __shared__ __align__(16) float w_s[48][64];
    __shared__ __align__(16) float wf_s[4][48][16];
    __shared__ float hb_s[48];
    __shared__ float4 x_s[16][64];

    const int bid  = blockIdx.x;
    const int p    = bid >> 1;         // level-5 node, grid-32
    const int qh   = bid & 1;
    const int tid  = threadIdx.x;

    const int r5 = p >> 5, c5 = p & 31;
    const int p4 = (r5 >> 1) * 16 + (c5 >> 1);
    const int c4 = ((r5 & 1) << 1) | (c5 & 1);
    const int nodeA = 85 + p4;
    const int nodeB = 341 + p;

    const float* FcA = (c4 == 0 ? ftl : c4 == 1 ? ftr : c4 == 2 ? fbl : fbr)
                       + (size_t)nodeA * 1024;

    stage_factor(fiA, fin + (size_t)nodeA * 1024, scale + (size_t)nodeA * 16, tid);
    stage_factor(FA,  FcA, nullptr, tid);
    stage_factor(fiB, fin + (size_t)nodeB * 1024, scale + (size_t)nodeB * 16, tid);
    {
        const float4* w4 = (const float4*)head_w;
        float4* d4 = (float4*)w_s;
        for (int k = tid; k < 768; k += 64) d4[k] = w4[k];
        const float4* wfp = (const float4*)(wf + (size_t)p * (4 * 48 * 16));
        float4* wfs = (float4*)wf_s;
        for (int k = tid; k < 768; k += 64) wfs[k] = wfp[k];
        if (tid < 48) hb_s[tid] = head_b[tid];
        const float4* xp = xin + ((size_t)p4 * 16) * 128 + qh * 64 + tid;
#pragma unroll
        for (int i4 = 0; i4 < 16; i4++)
            x_s[i4][tid] = xp[i4 * 128];
    }
    __syncthreads();

    // ---- level 4: x5 = x4 + F4^T lat4 (in own smem column)
    {
        float lat4[16]; u64 lp[16];
        lat_from_smem(lat4, fiA, x_s, tid);
        duppack16(lp, lat4);
        update_smem(x_s, FA, lp, tid);
    }

    // ---- level 5 lat + wx = W x5 + b, single pass over x
    float lat[16], wx[48];
    {
        u64 latacc[16], wxp[48];
#pragma unroll
        for (int r = 0; r < 16; r++) latacc[r] = 0ull;
#pragma unroll
        for (int k = 0; k < 48; k++) wxp[k] = 0ull;

#pragma unroll 2
        for (int i4 = 0; i4 < 16; i4++) {
            ulonglong2 xv = *(const ulonglong2*)&x_s[i4][tid];
#pragma unroll
            for (int r = 0; r < 16; r++) {
                ulonglong2 f = *(const ulonglong2*)&fiB[r][i4 * 4];
                fma2(latacc[r], xv.x, f.x);
                fma2(latacc[r], xv.y, f.y);
            }
#pragma unroll
            for (int k = 0; k < 48; k++) {
                ulonglong2 wv = *(const ulonglong2*)&w_s[k][i4 * 4];
                fma2(wxp[k], xv.x, wv.x);
                fma2(wxp[k], xv.y, wv.y);
            }
        }
#pragma unroll
        for (int r = 0; r < 16; r++) lat[r] = fold2(latacc[r]);
#pragma unroll
        for (int k = 0; k < 48; k++) wx[k] = fold2(wxp[k]) + hb_s[k];
    }

    // ---- children: y = wx + WF_c * lat -> pixels
    u64 latq[8];
#pragma unroll
    for (int j = 0; j < 8; j++) latq[j] = pack2(lat[2*j], lat[2*j + 1]);

    const int b  = qh * 64 + tid;
    const int gr = p >> 5, gc = p & 31;

#pragma unroll 1
    for (int c = 0; c < 4; c++) {
        const int cn = (2 * gr + (c >> 1)) * 64 + 2 * gc + (c & 1);

        float acc[48];
#pragma unroll
        for (int k = 0; k < 48; k++) {
            const ulonglong2* wfr = (const ulonglong2*)&wf_s[c][k][0];
            u64 a = 0ull;
#pragma unroll
            for (int j = 0; j < 4; j++) {
                ulonglong2 f = wfr[j];
                fma2(a, latq[2*j],     f.x);
                fma2(a, latq[2*j + 1], f.y);
            }
            acc[k] = wx[k] + fold2(a);
        }

        const int sr = cn >> 6, sc = cn & 63;
#pragma unroll
        for (int oc = 0; oc < 3; oc++) {
#pragma unroll
            for (int pr = 0; pr < 4; pr++) {
                float4 v = make_float4(acc[pr * 12 + 0 + oc],
                                       acc[pr * 12 + 3 + oc],
                                       acc[pr * 12 + 6 + oc],
                                       acc[pr * 12 + 9 + oc]);
                size_t row = (size_t)(b * 3 + oc) * 256 + (sr * 4 + pr);
                *(float4*)(out + row * 256 + sc * 4) = v;
            }
        }
    }
}

// ---------------------------------------------------------------------------
extern "C" void kernel_launch(void* const* d_in, const int* in_sizes, int n_in,
                              void* d_out, int out_size)
{
    const float* x      = (const float*)d_in[0];
    const float* fin    = (const float*)d_in[1];
    const float* ftl    = (const float*)d_in[2];
    const float* ftr    = (const float*)d_in[3];
    const float* fbl    = (const float*)d_in[4];
    const float* fbr    = (const float*)d_in[5];
    const float* scale  = (const float*)d_in[6];
    const float* head_w = (const float*)d_in[7];
    const float* head_b = (const float*)d_in[8];
    float* out = (float*)d_out;

    float4 *x2, *x4;
    float  *wfb;
    cudaGetSymbolAddress((void**)&x2,  g_x2);
    cudaGetSymbolAddress((void**)&x4,  g_x4);
    cudaGetSymbolAddress((void**)&wfb, g_wf);

    qt_wf_kernel<<<4096, 64>>>(ftl, ftr, fbl, fbr, head_w, wfb);
    qt_l01<<<32,  64>>>(x,  x2, fin, ftl, ftr, fbl, fbr, scale);
    qt_l23<<<512, 64>>>(x2, x4, fin, ftl, ftr, fbl, fbr, scale);
    qt_l45_head<<<2048, 64>>>(x4, fin, ftl, ftr, fbl, fbr, scale,
                              wfb, head_w, head_b, out);
}

// round 8
// speedup vs baseline: 1.2483x; 1.2483x over previous
#include <cuda_runtime.h>
#include <cstdint>

// ---------------------------------------------------------------------------
// QuadTreeDecoder round 8
//  - packed f32x2 FMA everywhere (as R7)
//  - qt_l45_head: 128 threads = (k-half) x (batch 64); per-thread register
//    state halved (wxp[24]) -> occupancy restored.
//  Activations node-major float4-interleaved: act[node][i4][b].
// ---------------------------------------------------------------------------

typedef unsigned long long u64;

__device__ float4 g_x2[(size_t)16  * 16 * 128];
__device__ float4 g_x4[(size_t)256 * 16 * 128];
__device__ float  g_wf[(size_t)1024 * 4 * 48 * 16];

// ---------------------------------------------------------------------------
__device__ __forceinline__ void fma2(u64& d, u64 a, u64 b) {
    asm("fma.rn.f32x2 %0, %1, %2, %3;" : "=l"(d) : "l"(a), "l"(b), "l"(d));
}
__device__ __forceinline__ u64 pack2(float lo, float hi) {
    u64 r; asm("mov.b64 %0, {%1, %2};" : "=l"(r) : "f"(lo), "f"(hi)); return r;
}
__device__ __forceinline__ float fold2(u64 v) {
    float lo, hi; asm("mov.b64 {%0, %1}, %2;" : "=f"(lo), "=f"(hi) : "l"(v));
    return lo + hi;
}

// ---------------------------------------------------------------------------
__device__ __forceinline__ void stage_factor_n(float dst[16][64], const float* __restrict__ src,
                                               const float* __restrict__ sc, int tid, int nthr)
{
    const float4* s4 = (const float4*)src;
    float4* d4 = (float4*)dst;
    if (sc) {
        for (int idx = tid; idx < 256; idx += nthr) {
            float4 v = s4[idx];
            float s = __ldg(&sc[idx >> 4]);
            v.x *= s; v.y *= s; v.z *= s; v.w *= s;
            d4[idx] = v;
        }
    } else {
        for (int idx = tid; idx < 256; idx += nthr)
            d4[idx] = s4[idx];
    }
}

__device__ __forceinline__ void lat_from_smem(float lat[16],
        const float (*__restrict__ fi)[64], const float4 (*__restrict__ x_s)[64], int col)
{
    u64 acc[16];
#pragma unroll
    for (int r = 0; r < 16; r++) acc[r] = 0ull;
#pragma unroll 4
    for (int i4 = 0; i4 < 16; i4++) {
        ulonglong2 xv = *(const ulonglong2*)&x_s[i4][col];
#pragma unroll
        for (int r = 0; r < 16; r++) {
            ulonglong2 f = *(const ulonglong2*)&fi[r][i4 * 4];
            fma2(acc[r], xv.x, f.x);
            fma2(acc[r], xv.y, f.y);
        }
    }
#pragma unroll
    for (int r = 0; r < 16; r++) lat[r] = fold2(acc[r]);
}

__device__ __forceinline__ void duppack16(u64 lp[16], const float lat[16]) {
#pragma unroll
    for (int r = 0; r < 16; r++) lp[r] = pack2(lat[r], lat[r]);
}

__device__ __forceinline__ void update_smem(float4 (*x_s)[64],
        const float (*__restrict__ F)[64], const u64 lp[16], int col)
{
#pragma unroll 4
    for (int o4 = 0; o4 < 16; o4++) {
        ulonglong2 a = *(const ulonglong2*)&x_s[o4][col];
#pragma unroll
        for (int r = 0; r < 16; r++) {
            ulonglong2 f = *(const ulonglong2*)&F[r][o4 * 4];
            fma2(a.x, lp[r], f.x);
            fma2(a.y, lp[r], f.y);
        }
        *(ulonglong2*)&x_s[o4][col] = a;
    }
}

__device__ __forceinline__ void emit_global(float4* __restrict__ op,
        const float4 (*__restrict__ x_s)[64],
        const float (*__restrict__ F)[64], const u64 lp[16], int col)
{
#pragma unroll 4
    for (int o4 = 0; o4 < 16; o4++) {
        ulonglong2 a = *(const ulonglong2*)&x_s[o4][col];
#pragma unroll
        for (int r = 0; r < 16; r++) {
            ulonglong2 f = *(const ulonglong2*)&F[r][o4 * 4];
            fma2(a.x, lp[r], f.x);
            fma2(a.y, lp[r], f.y);
        }
        *(ulonglong2*)&op[o4 * 128] = a;
    }
}

// ---------------------------------------------------------------------------
// WF[p][c][k][r] = sum_o head_w[k][o] * F_c[341+p][r][o].  4096 blocks x 64.
// ---------------------------------------------------------------------------
__global__ __launch_bounds__(64)
void qt_wf_kernel(const float* __restrict__ ftl, const float* __restrict__ ftr,
                  const float* __restrict__ fbl, const float* __restrict__ fbr,
                  const float* __restrict__ head_w, float* __restrict__ wf)
{
    __shared__ __align__(16) float F_s[16][64];

    const int bid = blockIdx.x;
    const int p   = bid >> 2;
    const int c   = bid & 3;
    const int tid = threadIdx.x;
    const int node = 341 + p;

    const float* Fc = (c == 0 ? ftl : c == 1 ? ftr : c == 2 ? fbl : fbr)
                      + (size_t)node * 1024;
    stage_factor_n(F_s, Fc, nullptr, tid, 64);
    __syncthreads();

    if (tid < 48) {
        const int k = tid;
        const ulonglong2* wrow = (const ulonglong2*)(head_w + (size_t)k * 64);
        u64 acc[16];
#pragma unroll
        for (int r = 0; r < 16; r++) acc[r] = 0ull;
#pragma unroll 4
        for (int i4 = 0; i4 < 16; i4++) {
            ulonglong2 wv = wrow[i4];
#pragma unroll
            for (int r = 0; r < 16; r++) {
                ulonglong2 f = *(const ulonglong2*)&F_s[r][i4 * 4];
                fma2(acc[r], wv.x, f.x);
                fma2(acc[r], wv.y, f.y);
            }
        }
        float* dst = wf + ((size_t)p * 4 + c) * (48 * 16) + (size_t)k * 16;
#pragma unroll
        for (int r = 0; r < 16; r += 4)
            *(float4*)(dst + r) = make_float4(fold2(acc[r]), fold2(acc[r+1]),
                                              fold2(acc[r+2]), fold2(acc[r+3]));
    }
}

// ---------------------------------------------------------------------------
// Levels 0+1 fused. bid = (p1*4 + c1)*2 + qh. 32 blocks x 64.
// ---------------------------------------------------------------------------
__global__ __launch_bounds__(64)
void qt_l01(const float* __restrict__ x0, float4* __restrict__ xout,
            const float* __restrict__ fin,
            const float* __restrict__ ftl, const float* __restrict__ ftr,
            const float* __restrict__ fbl, const float* __restrict__ fbr,
            const float* __restrict__ scale)
{
    __shared__ __align__(16) float fiA[16][64], FA[16][64], fiB[16][64], FB[16][64];
    __shared__ float4 x_s[16][64];

    const int bid = blockIdx.x;
    const int p1  = bid >> 3;
    const int c1  = (bid >> 1) & 3;
    const int qh  = bid & 1;
    const int tid = threadIdx.x;

    const float* FcA = (p1 == 0 ? ftl : p1 == 1 ? ftr : p1 == 2 ? fbl : fbr);
    const int nodeB = 1 + p1;
    const float* FcB = (c1 == 0 ? ftl : c1 == 1 ? ftr : c1 == 2 ? fbl : fbr)
                       + (size_t)nodeB * 1024;

    stage_factor_n(fiA, fin, scale, tid, 64);
    stage_factor_n(FA,  FcA, nullptr, tid, 64);
    stage_factor_n(fiB, fin + (size_t)nodeB * 1024, scale + (size_t)nodeB * 16, tid, 64);
    stage_factor_n(FB,  FcB, nullptr, tid, 64);
    {
        const int b = qh * 64 + tid;
        const float4* xp = (const float4*)(x0 + (size_t)b * 64);
#pragma unroll
        for (int i4 = 0; i4 < 16; i4++)
            x_s[i4][tid] = xp[i4];
    }
    __syncthreads();

    float lat[16]; u64 lp[16];
    lat_from_smem(lat, fiA, x_s, tid);
    duppack16(lp, lat);
    update_smem(x_s, FA, lp, tid);
    lat_from_smem(lat, fiB, x_s, tid);
    duppack16(lp, lat);

    const int gr = p1 >> 1, gc = p1 & 1;
    const int cn = (2 * gr + (c1 >> 1)) * 4 + 2 * gc + (c1 & 1);
    float4* op = xout + ((size_t)cn * 16) * 128 + qh * 64 + tid;
    emit_global(op, x_s, FB, lp, tid);
}

// ---------------------------------------------------------------------------
// Levels 2+3 fused. bid = (p3*4 + c3)*2 + qh. 512 blocks x 64.
// ---------------------------------------------------------------------------
__global__ __launch_bounds__(64)
void qt_l23(const float4* __restrict__ xin, float4* __restrict__ xout,
            const float* __restrict__ fin,
            const float* __restrict__ ftl, const float* __restrict__ ftr,
            const float* __restrict__ fbl, const float* __restrict__ fbr,
            const float* __restrict__ scale)
{
    __shared__ __align__(16) float fiA[16][64], FA[16][64], fiB[16][64], FB[16][64];
    __shared__ float4 x_s[16][64];

    const int bid = blockIdx.x;
    const int p3  = bid >> 3;
    const int c3  = (bid >> 1) & 3;
    const int qh  = bid & 1;
    const int tid = threadIdx.x;

    const int r3 = p3 >> 3, k3 = p3 & 7;
    const int p2 = (r3 >> 1) * 4 + (k3 >> 1);
    const int c2 = ((r3 & 1) << 1) | (k3 & 1);

    const int nodeA = 5 + p2;
    const int nodeB = 21 + p3;
    const float* FcA = (c2 == 0 ? ftl : c2 == 1 ? ftr : c2 == 2 ? fbl : fbr)
                       + (size_t)nodeA * 1024;
    const float* FcB = (c3 == 0 ? ftl : c3 == 1 ? ftr : c3 == 2 ? fbl : fbr)
                       + (size_t)nodeB * 1024;

    stage_factor_n(fiA, fin + (size_t)nodeA * 1024, scale + (size_t)nodeA * 16, tid, 64);
    stage_factor_n(FA,  FcA, nullptr, tid, 64);
    stage_factor_n(fiB, fin + (size_t)nodeB * 1024, scale + (size_t)nodeB * 16, tid, 64);
    stage_factor_n(FB,  FcB, nullptr, tid, 64);
    {
        const float4* xp = xin + ((size_t)p2 * 16) * 128 + qh * 64 + tid;
#pragma unroll
        for (int i4 = 0; i4 < 16; i4++)
            x_s[i4][tid] = xp[i4 * 128];
    }
    __syncthreads();

    float lat[16]; u64 lp[16];
    lat_from_smem(lat, fiA, x_s, tid);
    duppack16(lp, lat);
    update_smem(x_s, FA, lp, tid);
    lat_from_smem(lat, fiB, x_s, tid);
    duppack16(lp, lat);

    const int gr = p3 >> 3, gc = p3 & 7;
    const int cn = (2 * gr + (c3 >> 1)) * 16 + 2 * gc + (c3 & 1);
    float4* op = xout + ((size_t)cn * 16) * 128 + qh * 64 + tid;
    emit_global(op, x_s, FB, lp, tid);
}

// ---------------------------------------------------------------------------
// Levels 4+5 + head. bid = p*2 + qh (2048 blocks), 128 threads = kh(2) x b(64).
// Each k-half computes 24 of 48 head outputs; level-4 smem update split by o4.
// ---------------------------------------------------------------------------
__global__ __launch_bounds__(128, 3)
void qt_l45_head(const float4* __restrict__ xin,
                 const float* __restrict__ fin,
                 const float* __restrict__ ftl, const float* __restrict__ ftr,
                 const float* __restrict__ fbl, const float* __restrict__ fbr,
                 const float* __restrict__ scale,
                 const float* __restrict__ wf,
                 const float* __restrict__ head_w, const float* __restrict__ head_b,
                 float* __restrict__ out)
{
    __shared__ __align__(16) float fiA[16][64], FA[16][64], fiB[16][64];
    __shared__ __align__(16) float w_s[48][64];
    __shared__ __align__(16) float wf_s[4][48][16];
    __shared__ float hb_s[48];
    __shared__ float4 x_s[16][64];

    const int bid  = blockIdx.x;
    const int p    = bid >> 1;         // level-5 node, grid-32
    const int qh   = bid & 1;
    const int tid  = threadIdx.x;
    const int col  = tid & 63;         // batch within half
    const int kh   = tid >> 6;         // k-half: 0 -> k 0..23, 1 -> k 24..47

    const int r5 = p >> 5, c5 = p & 31;
    const int p4 = (r5 >> 1) * 16 + (c5 >> 1);
    const int c4 = ((r5 & 1) << 1) | (c5 & 1);
    const int nodeA = 85 + p4;
    const int nodeB = 341 + p;

    const float* FcA = (c4 == 0 ? ftl : c4 == 1 ? ftr : c4 == 2 ? fbl : fbr)
                       + (size_t)nodeA * 1024;

    stage_factor_n(fiA, fin + (size_t)nodeA * 1024, scale + (size_t)nodeA * 16, tid, 128);
    stage_factor_n(FA,  FcA, nullptr, tid, 128);
    stage_factor_n(fiB, fin + (size_t)nodeB * 1024, scale + (size_t)nodeB * 16, tid, 128);
    {
        const float4* w4 = (const float4*)head_w;
        float4* d4 = (float4*)w_s;
        for (int k = tid; k < 768; k += 128) d4[k] = w4[k];
        const float4* wfp = (const float4*)(wf + (size_t)p * (4 * 48 * 16));
        float4* wfs = (float4*)wf_s;
        for (int k = tid; k < 768; k += 128) wfs[k] = wfp[k];
        if (tid < 48) hb_s[tid] = head_b[tid];
        // x: 1024 float4 entries, 8 per thread, coalesced
        const float4* xbase = xin + (size_t)p4 * 16 * 128 + qh * 64;
#pragma unroll
        for (int j = 0; j < 8; j++) {
            int idx = tid + j * 128;             // i4*64 + c
            x_s[idx >> 6][idx & 63] = xbase[(idx >> 6) * 128 + (idx & 63)];
        }
    }
    __syncthreads();

    // ---- level 4 lat (both k-halves compute; reads must finish before update)
    float lat[16]; u64 lp[16];
    lat_from_smem(lat, fiA, x_s, col);
    duppack16(lp, lat);
    __syncthreads();

    // ---- level-4 update split by o4 half: kh updates o4 in [kh*8, kh*8+8)
    {
#pragma unroll 4
        for (int o4 = kh * 8; o4 < kh * 8 + 8; o4++) {
            ulonglong2 a = *(const ulonglong2*)&x_s[o4][col];
#pragma unroll
            for (int r = 0; r < 16; r++) {
                ulonglong2 f = *(const ulonglong2*)&FA[r][o4 * 4];
                fma2(a.x, lp[r], f.x);
                fma2(a.y, lp[r], f.y);
            }
            *(ulonglong2*)&x_s[o4][col] = a;
        }
    }
    __syncthreads();

    // ---- level-5 lat (redundant per k-half)
    lat_from_smem(lat, fiB, x_s, col);
    u64 latq[8];
#pragma unroll
    for (int j = 0; j < 8; j++) latq[j] = pack2(lat[2*j], lat[2*j + 1]);

    // ---- wx for this thread's 24 k's
    const int k0 = kh * 24;
    float wx[24];
    {
        u64 wxp[24];
#pragma unroll
        for (int k = 0; k < 24; k++) wxp[k] = 0ull;
#pragma unroll 2
        for (int i4 = 0; i4 < 16; i4++) {
            ulonglong2 xv = *(const ulonglong2*)&x_s[i4][col];
#pragma unroll
            for (int k = 0; k < 24; k++) {
                ulonglong2 wv = *(const ulonglong2*)&w_s[k0 + k][i4 * 4];
                fma2(wxp[k], xv.x, wv.x);
                fma2(wxp[k], xv.y, wv.y);
            }
        }
#pragma unroll
        for (int k = 0; k < 24; k++) wx[k] = fold2(wxp[k]) + hb_s[k0 + k];
    }

    // ---- children -> pixels (this k-half covers pr = kh*2 .. kh*2+1)
    const int b  = qh * 64 + col;
    const int gr = p >> 5, gc = p & 31;

#pragma unroll 1
    for (int c = 0; c < 4; c++) {
        const int cn = (2 * gr + (c >> 1)) * 64 + 2 * gc + (c & 1);

        float acc[24];
#pragma unroll
        for (int k = 0; k < 24; k++) {
            const ulonglong2* wfr = (const ulonglong2*)&wf_s[c][k0 + k][0];
            u64 a = 0ull;
#pragma unroll
            for (int j = 0; j < 4; j++) {
                ulonglong2 f = wfr[j];
                fma2(a, latq[2*j],     f.x);
                fma2(a, latq[2*j + 1], f.y);
            }
            acc[k] = wx[k] + fold2(a);
        }

        const int sr = cn >> 6, sc = cn & 63;
#pragma unroll
        for (int oc = 0; oc < 3; oc++) {
#pragma unroll
            for (int prl = 0; prl < 2; prl++) {
                const int pr = kh * 2 + prl;
                float4 v = make_float4(acc[prl * 12 + 0 + oc],
                                       acc[prl * 12 + 3 + oc],
                                       acc[prl * 12 + 6 + oc],
                                       acc[prl * 12 + 9 + oc]);
                size_t row = (size_t)(b * 3 + oc) * 256 + (sr * 4 + pr);
                *(float4*)(out + row * 256 + sc * 4) = v;
            }
        }
    }
}

// ---------------------------------------------------------------------------
extern "C" void kernel_launch(void* const* d_in, const int* in_sizes, int n_in,
                              void* d_out, int out_size)
{
    const float* x      = (const float*)d_in[0];
    const float* fin    = (const float*)d_in[1];
    const float* ftl    = (const float*)d_in[2];
    const float* ftr    = (const float*)d_in[3];
    const float* fbl    = (const float*)d_in[4];
    const float* fbr    = (const float*)d_in[5];
    const float* scale  = (const float*)d_in[6];
    const float* head_w = (const float*)d_in[7];
    const float* head_b = (const float*)d_in[8];
    float* out = (float*)d_out;

    float4 *x2, *x4;
    float  *wfb;
    cudaGetSymbolAddress((void**)&x2,  g_x2);
    cudaGetSymbolAddress((void**)&x4,  g_x4);
    cudaGetSymbolAddress((void**)&wfb, g_wf);

    qt_wf_kernel<<<4096, 64>>>(ftl, ftr, fbl, fbr, head_w, wfb);
    qt_l01<<<32,  64>>>(x,  x2, fin, ftl, ftr, fbl, fbr, scale);
    qt_l23<<<512, 64>>>(x2, x4, fin, ftl, ftr, fbl, fbr, scale);
    qt_l45_head<<<2048, 128>>>(x4, fin, ftl, ftr, fbl, fbr, scale,
                               wfb, head_w, head_b, out);
}

// round 9
// speedup vs baseline: 1.3055x; 1.0459x over previous
#include <cuda_runtime.h>
#include <cstdint>

// ---------------------------------------------------------------------------
// QuadTreeDecoder round 9
//  qt_l45_head restructured: 128 thr = kq(4) x col(32); cooperative lat phases
//  via smem (no redundant recompute); wf_s aliases dead factor smem.
//  Packed f32x2 FMA everywhere. Activations act[node][i4][b] float4-interleaved.
// ---------------------------------------------------------------------------

typedef unsigned long long u64;

__device__ float4 g_x2[(size_t)16  * 16 * 128];
__device__ float4 g_x4[(size_t)256 * 16 * 128];
__device__ float  g_wf[(size_t)1024 * 4 * 48 * 16];

// ---------------------------------------------------------------------------
__device__ __forceinline__ void fma2(u64& d, u64 a, u64 b) {
    asm("fma.rn.f32x2 %0, %1, %2, %3;" : "=l"(d) : "l"(a), "l"(b), "l"(d));
}
__device__ __forceinline__ u64 pack2(float lo, float hi) {
    u64 r; asm("mov.b64 %0, {%1, %2};" : "=l"(r) : "f"(lo), "f"(hi)); return r;
}
__device__ __forceinline__ float fold2(u64 v) {
    float lo, hi; asm("mov.b64 {%0, %1}, %2;" : "=f"(lo), "=f"(hi) : "l"(v));
    return lo + hi;
}

// ---------------------------------------------------------------------------
__device__ __forceinline__ void stage_factor_n(float dst[16][64], const float* __restrict__ src,
                                               const float* __restrict__ sc, int tid, int nthr)
{
    const float4* s4 = (const float4*)src;
    float4* d4 = (float4*)dst;
    if (sc) {
        for (int idx = tid; idx < 256; idx += nthr) {
            float4 v = s4[idx];
            float s = __ldg(&sc[idx >> 4]);
            v.x *= s; v.y *= s; v.z *= s; v.w *= s;
            d4[idx] = v;
        }
    } else {
        for (int idx = tid; idx < 256; idx += nthr)
            d4[idx] = s4[idx];
    }
}

__device__ __forceinline__ void lat_from_smem(float lat[16],
        const float (*__restrict__ fi)[64], const float4 (*__restrict__ x_s)[64], int col)
{
    u64 acc[16];
#pragma unroll
    for (int r = 0; r < 16; r++) acc[r] = 0ull;
#pragma unroll 4
    for (int i4 = 0; i4 < 16; i4++) {
        ulonglong2 xv = *(const ulonglong2*)&x_s[i4][col];
#pragma unroll
        for (int r = 0; r < 16; r++) {
            ulonglong2 f = *(const ulonglong2*)&fi[r][i4 * 4];
            fma2(acc[r], xv.x, f.x);
            fma2(acc[r], xv.y, f.y);
        }
    }
#pragma unroll
    for (int r = 0; r < 16; r++) lat[r] = fold2(acc[r]);
}

__device__ __forceinline__ void duppack16(u64 lp[16], const float lat[16]) {
#pragma unroll
    for (int r = 0; r < 16; r++) lp[r] = pack2(lat[r], lat[r]);
}

__device__ __forceinline__ void update_smem(float4 (*x_s)[64],
        const float (*__restrict__ F)[64], const u64 lp[16], int col)
{
#pragma unroll 4
    for (int o4 = 0; o4 < 16; o4++) {
        ulonglong2 a = *(const ulonglong2*)&x_s[o4][col];
#pragma unroll
        for (int r = 0; r < 16; r++) {
            ulonglong2 f = *(const ulonglong2*)&F[r][o4 * 4];
            fma2(a.x, lp[r], f.x);
            fma2(a.y, lp[r], f.y);
        }
        *(ulonglong2*)&x_s[o4][col] = a;
    }
}

__device__ __forceinline__ void emit_global(float4* __restrict__ op,
        const float4 (*__restrict__ x_s)[64],
        const float (*__restrict__ F)[64], const u64 lp[16], int col)
{
#pragma unroll 4
    for (int o4 = 0; o4 < 16; o4++) {
        ulonglong2 a = *(const ulonglong2*)&x_s[o4][col];
#pragma unroll
        for (int r = 0; r < 16; r++) {
            ulonglong2 f = *(const ulonglong2*)&F[r][o4 * 4];
            fma2(a.x, lp[r], f.x);
            fma2(a.y, lp[r], f.y);
        }
        *(ulonglong2*)&op[o4 * 128] = a;
    }
}

// ---------------------------------------------------------------------------
// WF[p][c][k][r] = sum_o head_w[k][o] * F_c[341+p][r][o].  4096 blocks x 64.
// ---------------------------------------------------------------------------
__global__ __launch_bounds__(64)
void qt_wf_kernel(const float* __restrict__ ftl, const float* __restrict__ ftr,
                  const float* __restrict__ fbl, const float* __restrict__ fbr,
                  const float* __restrict__ head_w, float* __restrict__ wf)
{
    __shared__ __align__(16) float F_s[16][64];

    const int bid = blockIdx.x;
    const int p   = bid >> 2;
    const int c   = bid & 3;
    const int tid = threadIdx.x;
    const int node = 341 + p;

    const float* Fc = (c == 0 ? ftl : c == 1 ? ftr : c == 2 ? fbl : fbr)
                      + (size_t)node * 1024;
    stage_factor_n(F_s, Fc, nullptr, tid, 64);
    __syncthreads();

    if (tid < 48) {
        const int k = tid;
        const ulonglong2* wrow = (const ulonglong2*)(head_w + (size_t)k * 64);
        u64 acc[16];
#pragma unroll
        for (int r = 0; r < 16; r++) acc[r] = 0ull;
#pragma unroll 4
        for (int i4 = 0; i4 < 16; i4++) {
            ulonglong2 wv = wrow[i4];
#pragma unroll
            for (int r = 0; r < 16; r++) {
                ulonglong2 f = *(const ulonglong2*)&F_s[r][i4 * 4];
                fma2(acc[r], wv.x, f.x);
                fma2(acc[r], wv.y, f.y);
            }
        }
        float* dst = wf + ((size_t)p * 4 + c) * (48 * 16) + (size_t)k * 16;
#pragma unroll
        for (int r = 0; r < 16; r += 4)
            *(float4*)(dst + r) = make_float4(fold2(acc[r]), fold2(acc[r+1]),
                                              fold2(acc[r+2]), fold2(acc[r+3]));
    }
}

// ---------------------------------------------------------------------------
// Levels 0+1 fused. bid = (p1*4 + c1)*2 + qh. 32 blocks x 64.
// ---------------------------------------------------------------------------
__global__ __launch_bounds__(64)
void qt_l01(const float* __restrict__ x0, float4* __restrict__ xout,
            const float* __restrict__ fin,
            const float* __restrict__ ftl, const float* __restrict__ ftr,
            const float* __restrict__ fbl, const float* __restrict__ fbr,
            const float* __restrict__ scale)
{
    __shared__ __align__(16) float fiA[16][64], FA[16][64], fiB[16][64], FB[16][64];
    __shared__ float4 x_s[16][64];

    const int bid = blockIdx.x;
    const int p1  = bid >> 3;
    const int c1  = (bid >> 1) & 3;
    const int qh  = bid & 1;
    const int tid = threadIdx.x;

    const float* FcA = (p1 == 0 ? ftl : p1 == 1 ? ftr : p1 == 2 ? fbl : fbr);
    const int nodeB = 1 + p1;
    const float* FcB = (c1 == 0 ? ftl : c1 == 1 ? ftr : c1 == 2 ? fbl : fbr)
                       + (size_t)nodeB * 1024;

    stage_factor_n(fiA, fin, scale, tid, 64);
    stage_factor_n(FA,  FcA, nullptr, tid, 64);
    stage_factor_n(fiB, fin + (size_t)nodeB * 1024, scale + (size_t)nodeB * 16, tid, 64);
    stage_factor_n(FB,  FcB, nullptr, tid, 64);
    {
        const int b = qh * 64 + tid;
        const float4* xp = (const float4*)(x0 + (size_t)b * 64);
#pragma unroll
        for (int i4 = 0; i4 < 16; i4++)
            x_s[i4][tid] = xp[i4];
    }
    __syncthreads();

    float lat[16]; u64 lp[16];
    lat_from_smem(lat, fiA, x_s, tid);
    duppack16(lp, lat);
    update_smem(x_s, FA, lp, tid);
    lat_from_smem(lat, fiB, x_s, tid);
    duppack16(lp, lat);

    const int gr = p1 >> 1, gc = p1 & 1;
    const int cn = (2 * gr + (c1 >> 1)) * 4 + 2 * gc + (c1 & 1);
    float4* op = xout + ((size_t)cn * 16) * 128 + qh * 64 + tid;
    emit_global(op, x_s, FB, lp, tid);
}

// ---------------------------------------------------------------------------
// Levels 2+3 fused. bid = (p3*4 + c3)*2 + qh. 512 blocks x 64.
// ---------------------------------------------------------------------------
__global__ __launch_bounds__(64)
void qt_l23(const float4* __restrict__ xin, float4* __restrict__ xout,
            const float* __restrict__ fin,
            const float* __restrict__ ftl, const float* __restrict__ ftr,
            const float* __restrict__ fbl, const float* __restrict__ fbr,
            const float* __restrict__ scale)
{
    __shared__ __align__(16) float fiA[16][64], FA[16][64], fiB[16][64], FB[16][64];
    __shared__ float4 x_s[16][64];

    const int bid = blockIdx.x;
    const int p3  = bid >> 3;
    const int c3  = (bid >> 1) & 3;
    const int qh  = bid & 1;
    const int tid = threadIdx.x;

    const int r3 = p3 >> 3, k3 = p3 & 7;
    const int p2 = (r3 >> 1) * 4 + (k3 >> 1);
    const int c2 = ((r3 & 1) << 1) | (k3 & 1);

    const int nodeA = 5 + p2;
    const int nodeB = 21 + p3;
    const float* FcA = (c2 == 0 ? ftl : c2 == 1 ? ftr : c2 == 2 ? fbl : fbr)
                       + (size_t)nodeA * 1024;
    const float* FcB = (c3 == 0 ? ftl : c3 == 1 ? ftr : c3 == 2 ? fbl : fbr)
                       + (size_t)nodeB * 1024;

    stage_factor_n(fiA, fin + (size_t)nodeA * 1024, scale + (size_t)nodeA * 16, tid, 64);
    stage_factor_n(FA,  FcA, nullptr, tid, 64);
    stage_factor_n(fiB, fin + (size_t)nodeB * 1024, scale + (size_t)nodeB * 16, tid, 64);
    stage_factor_n(FB,  FcB, nullptr, tid, 64);
    {
        const float4* xp = xin + ((size_t)p2 * 16) * 128 + qh * 64 + tid;
#pragma unroll
        for (int i4 = 0; i4 < 16; i4++)
            x_s[i4][tid] = xp[i4 * 128];
    }
    __syncthreads();

    float lat[16]; u64 lp[16];
    lat_from_smem(lat, fiA, x_s, tid);
    duppack16(lp, lat);
    update_smem(x_s, FA, lp, tid);
    lat_from_smem(lat, fiB, x_s, tid);
    duppack16(lp, lat);

    const int gr = p3 >> 3, gc = p3 & 7;
    const int cn = (2 * gr + (c3 >> 1)) * 16 + 2 * gc + (c3 & 1);
    float4* op = xout + ((size_t)cn * 16) * 128 + qh * 64 + tid;
    emit_global(op, x_s, FB, lp, tid);
}

// ---------------------------------------------------------------------------
// Levels 4+5 + head. bid = p*4 + q4 (4096 blocks), 128 threads = kq(4) x col(32).
// Phase-cooperative: lat4/lat5 computed in r-quarters into lat_s; x update in
// o4-quarters; each thread owns 12 head outputs (k = kq*12 + kk, pr == kq).
// ---------------------------------------------------------------------------
__global__ __launch_bounds__(128, 4)
void qt_l45_head(const float4* __restrict__ xin,
                 const float* __restrict__ fin,
                 const float* __restrict__ ftl, const float* __restrict__ ftr,
                 const float* __restrict__ fbl, const float* __restrict__ fbr,
                 const float* __restrict__ scale,
                 const float* __restrict__ wf,
                 const float* __restrict__ head_w, const float* __restrict__ head_b,
                 float* __restrict__ out)
{
    // fac_s holds fiA|FA|fiB during levels, then is re-used for wf (3072 floats).
    __shared__ __align__(16) float fac_s[3072];
    __shared__ __align__(16) float w_s[48][64];
    __shared__ __align__(16) float4 x_s[16][32];
    __shared__ float lat_s[16][32];
    __shared__ float hb_s[48];

    float (*fiA)[64] = (float (*)[64])(fac_s);
    float (*FA)[64]  = (float (*)[64])(fac_s + 1024);
    float (*fiB)[64] = (float (*)[64])(fac_s + 2048);

    const int bid = blockIdx.x;
    const int p   = bid >> 2;          // level-5 node, grid-32 order
    const int q4  = bid & 3;           // batch quarter
    const int tid = threadIdx.x;
    const int col = tid & 31;          // batch within quarter
    const int kq  = tid >> 5;          // k-quarter: k in [kq*12, kq*12+12)

    const int r5 = p >> 5, c5 = p & 31;
    const int p4 = (r5 >> 1) * 16 + (c5 >> 1);
    const int c4 = ((r5 & 1) << 1) | (c5 & 1);
    const int nodeA = 85 + p4;
    const int nodeB = 341 + p;

    const float* FcA = (c4 == 0 ? ftl : c4 == 1 ? ftr : c4 == 2 ? fbl : fbr)
                       + (size_t)nodeA * 1024;

    stage_factor_n(fiA, fin + (size_t)nodeA * 1024, scale + (size_t)nodeA * 16, tid, 128);
    stage_factor_n(FA,  FcA, nullptr, tid, 128);
    stage_factor_n(fiB, fin + (size_t)nodeB * 1024, scale + (size_t)nodeB * 16, tid, 128);
    {
        const float4* w4 = (const float4*)head_w;
        float4* d4 = (float4*)w_s;
        for (int k = tid; k < 768; k += 128) d4[k] = w4[k];
        if (tid < 48) hb_s[tid] = head_b[tid];
        // x: 512 float4, 4 per thread
        const float4* xbase = xin + (size_t)p4 * 16 * 128 + q4 * 32;
#pragma unroll
        for (int j = 0; j < 4; j++) {
            int idx = tid + j * 128;             // i4*32 + c
            x_s[idx >> 5][idx & 31] = xbase[(idx >> 5) * 128 + (idx & 31)];
        }
    }
    __syncthreads();

    const int rq = kq * 4;

    // ---- P1: lat4 r-quarter for own col -> lat_s
    {
        u64 a4[4];
#pragma unroll
        for (int rr = 0; rr < 4; rr++) a4[rr] = 0ull;
#pragma unroll 4
        for (int i4 = 0; i4 < 16; i4++) {
            ulonglong2 xv = *(const ulonglong2*)&x_s[i4][col];
#pragma unroll
            for (int rr = 0; rr < 4; rr++) {
                ulonglong2 f = *(const ulonglong2*)&fiA[rq + rr][i4 * 4];
                fma2(a4[rr], xv.x, f.x);
                fma2(a4[rr], xv.y, f.y);
            }
        }
#pragma unroll
        for (int rr = 0; rr < 4; rr++) lat_s[rq + rr][col] = fold2(a4[rr]);
    }
    __syncthreads();

    // ---- P2: x update, o4-quarter for own col
    {
        u64 lp[16];
#pragma unroll
        for (int r = 0; r < 16; r++) {
            float v = lat_s[r][col];
            lp[r] = pack2(v, v);
        }
#pragma unroll
        for (int oo = 0; oo < 4; oo++) {
            const int o4 = rq + oo;
            ulonglong2 a = *(const ulonglong2*)&x_s[o4][col];
#pragma unroll
            for (int r = 0; r < 16; r++) {
                ulonglong2 f = *(const ulonglong2*)&FA[r][o4 * 4];
                fma2(a.x, lp[r], f.x);
                fma2(a.y, lp[r], f.y);
            }
            *(ulonglong2*)&x_s[o4][col] = a;
        }
    }
    __syncthreads();

    // ---- P3: lat5 r-quarter -> lat_s (overwrites lat4, safe after sync)
    {
        u64 a4[4];
#pragma unroll
        for (int rr = 0; rr < 4; rr++) a4[rr] = 0ull;
#pragma unroll 4
        for (int i4 = 0; i4 < 16; i4++) {
            ulonglong2 xv = *(const ulonglong2*)&x_s[i4][col];
#pragma unroll
            for (int rr = 0; rr < 4; rr++) {
                ulonglong2 f = *(const ulonglong2*)&fiB[rq + rr][i4 * 4];
                fma2(a4[rr], xv.x, f.x);
                fma2(a4[rr], xv.y, f.y);
            }
        }
#pragma unroll
        for (int rr = 0; rr < 4; rr++) lat_s[rq + rr][col] = fold2(a4[rr]);
    }
    __syncthreads();

    // ---- P4: stage wf into fac_s (factors dead) + compute wx (independent)
    {
        const float4* wfp = (const float4*)(wf + (size_t)p * 3072);
        float4* wfs = (float4*)fac_s;
        for (int k = tid; k < 768; k += 128) wfs[k] = wfp[k];
    }

    const int k0 = kq * 12;
    float wx[12];
    {
        u64 wxp[12];
#pragma unroll
        for (int kk = 0; kk < 12; kk++) wxp[kk] = 0ull;
#pragma unroll 2
        for (int i4 = 0; i4 < 16; i4++) {
            ulonglong2 xv = *(const ulonglong2*)&x_s[i4][col];
#pragma unroll
            for (int kk = 0; kk < 12; kk++) {
                ulonglong2 wv = *(const ulonglong2*)&w_s[k0 + kk][i4 * 4];
                fma2(wxp[kk], xv.x, wv.x);
                fma2(wxp[kk], xv.y, wv.y);
            }
        }
#pragma unroll
        for (int kk = 0; kk < 12; kk++) wx[kk] = fold2(wxp[kk]) + hb_s[k0 + kk];
    }

    // pack lat5 for children
    u64 latq[8];
#pragma unroll
    for (int j = 0; j < 8; j++)
        latq[j] = pack2(lat_s[2*j][col], lat_s[2*j + 1][col]);

    __syncthreads();   // wf_s (fac_s) ready

    const float (*wf_s)[16] = (const float (*)[16])fac_s;   // [c*48 + k][16]

    const int b  = q4 * 32 + col;
    const int gr = r5, gc = c5;

#pragma unroll 1
    for (int c = 0; c < 4; c++) {
        const int cn = (2 * gr + (c >> 1)) * 64 + 2 * gc + (c & 1);

        float acc[12];
#pragma unroll
        for (int kk = 0; kk < 12; kk++) {
            const ulonglong2* wfr = (const ulonglong2*)&wf_s[c * 48 + k0 + kk][0];
            u64 a = 0ull;
#pragma unroll
            for (int j = 0; j < 4; j++) {
                ulonglong2 f = wfr[j];
                fma2(a, latq[2*j],     f.x);
                fma2(a, latq[2*j + 1], f.y);
            }
            acc[kk] = wx[kk] + fold2(a);
        }

        // k = kq*12 + pc*3 + oc  ->  pr == kq
        const int sr = cn >> 6, sc = cn & 63;
#pragma unroll
        for (int oc = 0; oc < 3; oc++) {
            float4 v = make_float4(acc[0 + oc], acc[3 + oc], acc[6 + oc], acc[9 + oc]);
            size_t row = (size_t)(b * 3 + oc) * 256 + (sr * 4 + kq);
            *(float4*)(out + row * 256 + sc * 4) = v;
        }
    }
}

// ---------------------------------------------------------------------------
extern "C" void kernel_launch(void* const* d_in, const int* in_sizes, int n_in,
                              void* d_out, int out_size)
{
    const float* x      = (const float*)d_in[0];
    const float* fin    = (const float*)d_in[1];
    const float* ftl    = (const float*)d_in[2];
    const float* ftr    = (const float*)d_in[3];
    const float* fbl    = (const float*)d_in[4];
    const float* fbr    = (const float*)d_in[5];
    const float* scale  = (const float*)d_in[6];
    const float* head_w = (const float*)d_in[7];
    const float* head_b = (const float*)d_in[8];
    float* out = (float*)d_out;

    float4 *x2, *x4;
    float  *wfb;
    cudaGetSymbolAddress((void**)&x2,  g_x2);
    cudaGetSymbolAddress((void**)&x4,  g_x4);
    cudaGetSymbolAddress((void**)&wfb, g_wf);

    qt_wf_kernel<<<4096, 64>>>(ftl, ftr, fbl, fbr, head_w, wfb);
    qt_l01<<<32,  64>>>(x,  x2, fin, ftl, ftr, fbl, fbr, scale);
    qt_l23<<<512, 64>>>(x2, x4, fin, ftl, ftr, fbl, fbr, scale);
    qt_l45_head<<<4096, 128>>>(x4, fin, ftl, ftr, fbl, fbr, scale,
                               wfb, head_w, head_b, out);
}